// round 8
// baseline (speedup 1.0000x reference)
#include <cuda_runtime.h>
#include <cuda_bf16.h>

#define BB   32
#define NN   16384
#define DD   64
#define KK   64
#define CPB  8
#define NCTA (BB*CPB)                 // 256
#define NT   512
#define NW   16
#define PTS  2048                     // points per CTA
#define PPT  4                        // points per thread
#define CROW 65                       // padded center row (conflict-free lane-per-center)

// ---------------- device globals (static scratch only) --------------------
__device__ unsigned long long g_slot[BB * KK];   // per (batch, round) packed argmax
__device__ unsigned int g_count = 0;             // barrier arrival counter
__device__ unsigned int g_gen   = 0;             // barrier generation

// R1/R7's PROVEN grid-wide barrier, verbatim. All 256 CTAs co-resident
// (occupancy 2 x 148+ SMs >= 256).
__device__ __forceinline__ void grid_sync() {
    __syncthreads();
    if (threadIdx.x == 0) {
        __threadfence();
        unsigned int gen = *(volatile unsigned int*)&g_gen;
        unsigned int prev = atomicAdd(&g_count, 1u);
        if (prev == NCTA - 1) {
            g_count = 0;
            __threadfence();
            *(volatile unsigned int*)&g_gen = gen + 1;
        } else {
            while (*(volatile unsigned int*)&g_gen == gen) { __nanosleep(64); }
        }
        __threadfence();
    }
    __syncthreads();
}

// ---- THE distance: R1's proven rounding order, used for EVERY (point,center)
// pair in the kernel. Four sequential 16-dim fmaf chains, ((s0+s1)+s2)+s3.
// Templated on the load path (bits are identical either way).
__device__ __forceinline__ float dist16x4_g(const float* __restrict__ px,
                                            const float* __restrict__ cen) {
    float s[4];
    #pragma unroll
    for (int g = 0; g < 4; ++g) {
        float acc = 0.f;
        #pragma unroll
        for (int h = 0; h < 4; ++h) {
            float4 v = __ldg((const float4*)(px + g * 16 + h * 4));
            const int b = g * 16 + h * 4;
            float d;
            d = v.x - cen[b + 0]; acc = fmaf(d, d, acc);
            d = v.y - cen[b + 1]; acc = fmaf(d, d, acc);
            d = v.z - cen[b + 2]; acc = fmaf(d, d, acc);
            d = v.w - cen[b + 3]; acc = fmaf(d, d, acc);
        }
        s[g] = acc;
    }
    return ((s[0] + s[1]) + s[2]) + s[3];
}
__device__ __forceinline__ float dist16x4_s(const float* __restrict__ pt,   // SMEM point
                                            const float* __restrict__ cen) { // SMEM center
    float s[4];
    #pragma unroll
    for (int g = 0; g < 4; ++g) {
        float acc = 0.f;
        #pragma unroll
        for (int i = 0; i < 16; ++i) {
            float d = pt[g * 16 + i] - cen[g * 16 + i];
            acc = fmaf(d, d, acc);
        }
        s[g] = acc;
    }
    return ((s[0] + s[1]) + s[2]) + s[3];
}

__device__ __forceinline__ unsigned long long warp_max_u64(unsigned long long v) {
    #pragma unroll
    for (int o = 16; o; o >>= 1) {
        unsigned long long u = __shfl_xor_sync(0xffffffffu, v, o);
        v = (v > u) ? v : u;
    }
    return v;
}
__device__ __forceinline__ float warp_min_f(float m) {
    #pragma unroll
    for (int o = 16; o; o >>= 1) m = fminf(m, __shfl_xor_sync(0xffffffffu, m, o));
    return m;
}

__global__ void __launch_bounds__(NT, 2)
kmpp_kernel(const float* __restrict__ data,
            const int*   __restrict__ first_idx,
            float*       __restrict__ out)
{
    __shared__ float s_c[KK][CROW];               // 16.6 KB: all centers, padded rows
    __shared__ __align__(16) float s_ub[PTS];     //  8 KB: upper bounds on min_d
    __shared__ unsigned char s_lk[PTS];           //  2 KB: #centers accounted
    __shared__ short s_work[PTS];                 //  4 KB: refresh worklist
    __shared__ __align__(16) float s_pt[NW][DD];  //  4 KB: per-warp staged point
    __shared__ unsigned long long s_red[NW];
    __shared__ unsigned int s_Ebits;
    __shared__ int s_widx, s_wcnt;

    const int t     = threadIdx.x;
    const int lane  = t & 31;
    const int wid   = t >> 5;
    const int cta   = blockIdx.x;
    const int batch = cta / CPB;
    const int chunk = cta % CPB;
    const int pbase = chunk * PTS;
    const float* bd = data + (size_t)batch * NN * DD;
    float* bout     = out  + (size_t)batch * KK * DD;
    const bool leader = (chunk == 0);

    // reset this run's argmax slots (8 per CTA covers BB*KK = 2048)
    if (t < KK * BB / NCTA)
        g_slot[cta * (KK * BB / NCTA) + t] = 0ULL;

    // center 0
    if (t < DD) {
        int i0 = first_idx[batch];
        float c = bd[(size_t)i0 * DD + t];
        s_c[0][t] = c;
        if (leader) bout[t] = c;
    }
    __syncthreads();

    // ---- init: exact distance to center 0 for every owned point
    #pragma unroll
    for (int j = 0; j < PPT; ++j) {
        int p = t * PPT + j;
        s_ub[p] = dist16x4_g(bd + (size_t)(pbase + p) * DD, &s_c[0][0]);
        s_lk[p] = 1;
    }
    grid_sync();   // slot resets visible before any atomicMax

    for (int k = 1; k < KK; ++k) {
        if (t == 0) { s_Ebits = 0u; s_wcnt = 0; }
        __syncthreads();

        // ---- (B) per-warp candidate: refresh this warp's max-ub point
        //      exactly. E = max of 16 exact min_d values <= round winner.
        {
            int base = wid * 128 + lane * 4;
            float4 u = *(const float4*)&s_ub[base];
            unsigned long long wb;
            {
                unsigned long long p0 = ((unsigned long long)__float_as_uint(u.x) << 32) | (unsigned)~(base + 0);
                unsigned long long p1 = ((unsigned long long)__float_as_uint(u.y) << 32) | (unsigned)~(base + 1);
                unsigned long long p2 = ((unsigned long long)__float_as_uint(u.z) << 32) | (unsigned)~(base + 2);
                unsigned long long p3 = ((unsigned long long)__float_as_uint(u.w) << 32) | (unsigned)~(base + 3);
                wb = p0 > p1 ? p0 : p1;
                wb = wb > p2 ? wb : p2;
                wb = wb > p3 ? wb : p3;
            }
            wb = warp_max_u64(wb);
            int p = (int)(~(unsigned)wb) & (PTS - 1);

            if (lane < 16)
                ((float4*)&s_pt[wid][0])[lane] =
                    __ldg(((const float4*)(bd + (size_t)(pbase + p) * DD)) + lane);
            __syncwarp();

            int   clk = s_lk[p];
            float m   = s_ub[p];
            for (int c = clk + lane; c < k; c += 32)
                m = fminf(m, dist16x4_s(&s_pt[wid][0], &s_c[c][0]));
            m = warp_min_f(m);
            if (lane == 0) {
                s_ub[p] = m;
                if (clk < k) s_lk[p] = (unsigned char)k;
                atomicMax(&s_Ebits, __float_as_uint(m));
            }
        }
        __syncthreads();
        const float E = __uint_as_float(s_Ebits);

        // ---- (C) worklist: points whose bound could still reach the winner
        #pragma unroll
        for (int j = 0; j < PPT; ++j) {
            int p = t * PPT + j;
            if (s_ub[p] >= E && (int)s_lk[p] < k) {
                int w = atomicAdd(&s_wcnt, 1);
                s_work[w] = (short)p;
            }
        }
        __syncthreads();
        const int W = s_wcnt;

        // ---- refresh worklist: warp per point, lane per center
        for (int i = wid; i < W; i += NW) {
            int p = s_work[i];
            if (lane < 16)
                ((float4*)&s_pt[wid][0])[lane] =
                    __ldg(((const float4*)(bd + (size_t)(pbase + p) * DD)) + lane);
            __syncwarp();
            int   clk = s_lk[p];
            float m   = s_ub[p];
            for (int c = clk + lane; c < k; c += 32)
                m = fminf(m, dist16x4_s(&s_pt[wid][0], &s_c[c][0]));
            m = warp_min_f(m);
            if (lane == 0) { s_ub[p] = m; s_lk[p] = (unsigned char)k; }
            __syncwarp();
        }
        __syncthreads();

        // ---- (D) per-batch argmax: pack (dist_bits, ~global_idx)
        unsigned long long best = 0ULL;
        #pragma unroll
        for (int j = 0; j < PPT; ++j) {
            int p = t * PPT + j;
            unsigned long long pk =
                ((unsigned long long)__float_as_uint(s_ub[p]) << 32) |
                (unsigned)~(pbase + p);
            best = (best > pk) ? best : pk;
        }
        best = warp_max_u64(best);
        if (lane == 0) s_red[wid] = best;
        __syncthreads();
        if (t == 0) {
            unsigned long long b = s_red[0];
            #pragma unroll
            for (int i = 1; i < NW; ++i) b = (b > s_red[i]) ? b : s_red[i];
            atomicMax(&g_slot[batch * KK + k], b);
        }

        grid_sync();   // all CTAs' maxima for round k deposited

        if (t == 0) {
            unsigned long long v = atomicAdd(&g_slot[batch * KK + k], 0ULL);
            s_widx = (int)(~(unsigned)v);
        }
        __syncthreads();

        // ---- (E) gather winner as center k; zero its bound locally
        int w = s_widx;
        if (t < DD) {
            float c = bd[(size_t)w * DD + t];
            s_c[k][t] = c;
            if (leader) bout[k * DD + t] = c;
        }
        if (t == NT - 1) {
            int wl = w - pbase;
            if (wl >= 0 && wl < PTS) { s_ub[wl] = 0.f; s_lk[wl] = (unsigned char)KK; }
        }
        __syncthreads();
    }
}

extern "C" void kernel_launch(void* const* d_in, const int* in_sizes, int n_in,
                              void* d_out, int out_size) {
    const float* data      = (const float*)d_in[0];   // (B, N, D) fp32
    const int*   first_idx = (const int*)d_in[1];     // (B,) int32
    float*       out       = (float*)d_out;           // (B, K, D) fp32
    (void)in_sizes; (void)n_in; (void)out_size;
    kmpp_kernel<<<NCTA, NT>>>(data, first_idx, out);
}

// round 9
// speedup vs baseline: 1.3189x; 1.3189x over previous
#include <cuda_runtime.h>
#include <cuda_bf16.h>

#define BB   32
#define NN   16384
#define DD   64
#define KK   64
#define CPB  8
#define NCTA (BB*CPB)                 // 256
#define NT   512
#define NW   16
#define PTS  2048                     // points per CTA
#define PPT  4                        // points per thread
#define CROW 65                       // padded center row

// ---------------- device globals (static scratch only) --------------------
__device__ unsigned long long g_slot[BB * KK];   // per (batch, round) packed argmax
__device__ unsigned int       g_cnt [BB * KK];   // per (batch, round) arrivals

__global__ void km_init() {
    int i = blockIdx.x * blockDim.x + threadIdx.x;
    if (i < BB * KK) { g_slot[i] = 0ULL; g_cnt[i] = 0u; }
}

// ---- THE distance: R1's PROVEN rounding order (rel_err 0.0 in R7/R8).
// Four sequential 16-dim fmaf chains, combined ((s0+s1)+s2)+s3.
__device__ __forceinline__ float dist16x4_g(const float* __restrict__ px,
                                            const float* __restrict__ cen) {
    float s[4];
    #pragma unroll
    for (int g = 0; g < 4; ++g) {
        float acc = 0.f;
        #pragma unroll
        for (int h = 0; h < 4; ++h) {
            float4 v = __ldg((const float4*)(px + g * 16 + h * 4));
            const int b = g * 16 + h * 4;
            float d;
            d = v.x - cen[b + 0]; acc = fmaf(d, d, acc);
            d = v.y - cen[b + 1]; acc = fmaf(d, d, acc);
            d = v.z - cen[b + 2]; acc = fmaf(d, d, acc);
            d = v.w - cen[b + 3]; acc = fmaf(d, d, acc);
        }
        s[g] = acc;
    }
    return ((s[0] + s[1]) + s[2]) + s[3];
}
__device__ __forceinline__ float dist16x4_s(const float* __restrict__ pt,
                                            const float* __restrict__ cen) {
    float s[4];
    #pragma unroll
    for (int g = 0; g < 4; ++g) {
        float acc = 0.f;
        #pragma unroll
        for (int i = 0; i < 16; ++i) {
            float d = pt[g * 16 + i] - cen[g * 16 + i];
            acc = fmaf(d, d, acc);
        }
        s[g] = acc;
    }
    return ((s[0] + s[1]) + s[2]) + s[3];
}

__device__ __forceinline__ unsigned long long warp_max_u64(unsigned long long v) {
    #pragma unroll
    for (int o = 16; o; o >>= 1) {
        unsigned long long u = __shfl_xor_sync(0xffffffffu, v, o);
        v = (v > u) ? v : u;
    }
    return v;
}
__device__ __forceinline__ float warp_min_f(float m) {
    #pragma unroll
    for (int o = 16; o; o >>= 1) m = fminf(m, __shfl_xor_sync(0xffffffffu, m, o));
    return m;
}

__global__ void __launch_bounds__(NT, 2)
kmpp_kernel(const float* __restrict__ data,
            const int*   __restrict__ first_idx,
            float*       __restrict__ out)
{
    __shared__ float s_c[KK][CROW];               // 16.6 KB: all centers
    __shared__ __align__(16) float s_ub[PTS];     //  8 KB: upper bounds on min_d
    __shared__ unsigned char s_lk[PTS];           //  2 KB: centers accounted so far
    __shared__ __align__(16) float s_pt[NW][DD];  //  4 KB: per-warp staged candidate
    __shared__ unsigned long long s_red[NW];
    __shared__ unsigned int s_Ebits;
    __shared__ int s_widx;

    const int t     = threadIdx.x;
    const int lane  = t & 31;
    const int wid   = t >> 5;
    const int cta   = blockIdx.x;
    const int batch = cta / CPB;
    const int chunk = cta % CPB;
    const int pbase = chunk * PTS;
    const float* bd = data + (size_t)batch * NN * DD;
    float* bout     = out  + (size_t)batch * KK * DD;
    const bool leader = (chunk == 0);

    // center 0
    if (t < DD) {
        int i0 = first_idx[batch];
        float c = bd[(size_t)i0 * DD + t];
        s_c[0][t] = c;
        if (leader) bout[t] = c;
    }
    __syncthreads();

    // ---- init: exact distance to center 0 for every owned point
    #pragma unroll
    for (int j = 0; j < PPT; ++j) {
        int p = t * PPT + j;
        s_ub[p] = dist16x4_g(bd + (size_t)(pbase + p) * DD, &s_c[0][0]);
        s_lk[p] = 1;
    }
    __syncthreads();

    for (int k = 1; k < KK; ++k) {
        if (t == 0) s_Ebits = 0u;
        __syncthreads();

        // ---- (B) per-warp candidate: fully refresh the warp's max-ub point.
        //      E = max of 16 exact min_d values => E <= round winner value.
        {
            int base = wid * 128 + lane * 4;
            float4 u = *(const float4*)&s_ub[base];
            unsigned long long wb;
            {
                unsigned long long p0 = ((unsigned long long)__float_as_uint(u.x) << 32) | (unsigned)~(base + 0);
                unsigned long long p1 = ((unsigned long long)__float_as_uint(u.y) << 32) | (unsigned)~(base + 1);
                unsigned long long p2 = ((unsigned long long)__float_as_uint(u.z) << 32) | (unsigned)~(base + 2);
                unsigned long long p3 = ((unsigned long long)__float_as_uint(u.w) << 32) | (unsigned)~(base + 3);
                wb = p0 > p1 ? p0 : p1;
                wb = wb > p2 ? wb : p2;
                wb = wb > p3 ? wb : p3;
            }
            wb = warp_max_u64(wb);
            int p = (int)(~(unsigned)wb) & (PTS - 1);

            if (lane < 16)
                ((float4*)&s_pt[wid][0])[lane] =
                    __ldg(((const float4*)(bd + (size_t)(pbase + p) * DD)) + lane);
            __syncwarp();

            int   clk = s_lk[p];
            float m   = s_ub[p];
            for (int c = clk + lane; c < k; c += 32)
                m = fminf(m, dist16x4_s(&s_pt[wid][0], &s_c[c][0]));
            m = warp_min_f(m);
            if (lane == 0) {
                s_ub[p] = m;
                if (clk < k) s_lk[p] = (unsigned char)k;
                atomicMax(&s_Ebits, __float_as_uint(m));
            }
        }
        __syncthreads();
        const float E = __uint_as_float(s_Ebits);

        // ---- (C) thread-per-point lazy refresh with per-center early exit.
        // Safe: winner (and any same-value smaller-index tie) has true >= E,
        // and m >= true throughout, so it never exits early -> exact.
        // Early-exited points end with m < E <= winner -> cannot affect argmax.
        #pragma unroll
        for (int j = 0; j < PPT; ++j) {
            int p = t * PPT + j;
            float m = s_ub[p];
            int   c = s_lk[p];
            if (m >= E && c < k) {
                const float* px = bd + (size_t)(pbase + p) * DD;
                do {
                    m = fminf(m, dist16x4_g(px, &s_c[c][0]));
                    ++c;
                } while (c < k && m >= E);
                s_ub[p] = m;
                s_lk[p] = (unsigned char)c;
            }
        }
        __syncthreads();

        // ---- (D) per-batch argmax: pack (dist_bits, ~global_idx)
        unsigned long long best = 0ULL;
        #pragma unroll
        for (int j = 0; j < PPT; ++j) {
            int p = t * PPT + j;
            unsigned long long pk =
                ((unsigned long long)__float_as_uint(s_ub[p]) << 32) |
                (unsigned)~(pbase + p);
            best = (best > pk) ? best : pk;
        }
        best = warp_max_u64(best);
        if (lane == 0) s_red[wid] = best;
        __syncthreads();
        if (t == 0) {
            unsigned long long b = s_red[0];
            #pragma unroll
            for (int i = 1; i < NW; ++i) b = (b > s_red[i]) ? b : s_red[i];
            // per-batch barrier: release -> arrive -> spin -> acquire -> read
            atomicMax(&g_slot[batch * KK + k], b);
            __threadfence();
            atomicAdd(&g_cnt[batch * KK + k], 1u);
            while (atomicAdd(&g_cnt[batch * KK + k], 0u) < (unsigned)CPB)
                __nanosleep(32);
            __threadfence();
            unsigned long long v = atomicAdd(&g_slot[batch * KK + k], 0ULL);
            s_widx = (int)(~(unsigned)v);
        }
        __syncthreads();

        // ---- (E) gather winner as center k; zero its bound locally
        int w = s_widx;
        if (t < DD) {
            float c = bd[(size_t)w * DD + t];
            s_c[k][t] = c;
            if (leader) bout[k * DD + t] = c;
        }
        if (t == NT - 1) {
            int wl = w - pbase;
            if (wl >= 0 && wl < PTS) { s_ub[wl] = 0.f; s_lk[wl] = (unsigned char)KK; }
        }
        __syncthreads();
    }
}

extern "C" void kernel_launch(void* const* d_in, const int* in_sizes, int n_in,
                              void* d_out, int out_size) {
    const float* data      = (const float*)d_in[0];   // (B, N, D) fp32
    const int*   first_idx = (const int*)d_in[1];     // (B,) int32
    float*       out       = (float*)d_out;           // (B, K, D) fp32
    (void)in_sizes; (void)n_in; (void)out_size;
    km_init<<<4, NT>>>();
    kmpp_kernel<<<NCTA, NT>>>(data, first_idx, out);
}

// round 10
// speedup vs baseline: 2.2119x; 1.6771x over previous
#include <cuda_runtime.h>
#include <cuda_bf16.h>

#define BB   32
#define NN   16384
#define DD   64
#define KK   64
#define CPB  8
#define NCTA (BB*CPB)                 // 256
#define NT   512
#define NW   16
#define PTS  2048                     // points per CTA
#define PPT  4                        // points per thread
#define CROW 65                       // padded center row (conflict-free)
#define LMAX 3                        // tier-1 max lag

// ---------------- device globals (static scratch only) --------------------
__device__ unsigned long long g_slot[BB * KK];   // per (batch, round) packed argmax
__device__ unsigned int       g_cnt [BB * KK];   // per (batch, round) arrivals

__global__ void km_init() {
    int i = blockIdx.x * blockDim.x + threadIdx.x;
    if (i < BB * KK) { g_slot[i] = 0ULL; g_cnt[i] = 0u; }
}

// ---- THE distance: R1's PROVEN rounding order (rel_err 0.0 in R7/R8/R9).
// Four sequential 16-dim fmaf chains, combined ((s0+s1)+s2)+s3.
__device__ __forceinline__ float dist16x4_g(const float* __restrict__ px,
                                            const float* __restrict__ cen) {
    float s[4];
    #pragma unroll
    for (int g = 0; g < 4; ++g) {
        float acc = 0.f;
        #pragma unroll
        for (int h = 0; h < 4; ++h) {
            float4 v = __ldg((const float4*)(px + g * 16 + h * 4));
            const int b = g * 16 + h * 4;
            float d;
            d = v.x - cen[b + 0]; acc = fmaf(d, d, acc);
            d = v.y - cen[b + 1]; acc = fmaf(d, d, acc);
            d = v.z - cen[b + 2]; acc = fmaf(d, d, acc);
            d = v.w - cen[b + 3]; acc = fmaf(d, d, acc);
        }
        s[g] = acc;
    }
    return ((s[0] + s[1]) + s[2]) + s[3];
}
__device__ __forceinline__ float dist16x4_s(const float* __restrict__ pt,
                                            const float* __restrict__ cen) {
    float s[4];
    #pragma unroll
    for (int g = 0; g < 4; ++g) {
        float acc = 0.f;
        #pragma unroll
        for (int i = 0; i < 16; ++i) {
            float d = pt[g * 16 + i] - cen[g * 16 + i];
            acc = fmaf(d, d, acc);
        }
        s[g] = acc;
    }
    return ((s[0] + s[1]) + s[2]) + s[3];
}

__device__ __forceinline__ unsigned long long warp_max_u64(unsigned long long v) {
    #pragma unroll
    for (int o = 16; o; o >>= 1) {
        unsigned long long u = __shfl_xor_sync(0xffffffffu, v, o);
        v = (v > u) ? v : u;
    }
    return v;
}
__device__ __forceinline__ float warp_min_f(float m) {
    #pragma unroll
    for (int o = 16; o; o >>= 1) m = fminf(m, __shfl_xor_sync(0xffffffffu, m, o));
    return m;
}

__global__ void __launch_bounds__(NT, 2)
kmpp_kernel(const float* __restrict__ data,
            const int*   __restrict__ first_idx,
            float*       __restrict__ out)
{
    __shared__ float s_c[KK][CROW];               // 16.6 KB: all centers
    __shared__ __align__(16) float s_ub[PTS];     //  8 KB: upper bounds on min_d
    __shared__ unsigned char s_lk[PTS];           //  2 KB: centers accounted
    __shared__ short s_work[PTS];                 //  4 KB: tier-2 worklist
    __shared__ __align__(16) float s_pt[NW][DD];  //  4 KB: per-warp staged point
    __shared__ unsigned long long s_red[NW];
    __shared__ unsigned int s_Ebits;
    __shared__ int s_widx, s_wcnt;

    const int t     = threadIdx.x;
    const int lane  = t & 31;
    const int wid   = t >> 5;
    const int cta   = blockIdx.x;
    const int batch = cta / CPB;
    const int chunk = cta % CPB;
    const int pbase = chunk * PTS;
    const float* bd = data + (size_t)batch * NN * DD;
    float* bout     = out  + (size_t)batch * KK * DD;
    const bool leader = (chunk == 0);

    // center 0
    if (t < DD) {
        int i0 = first_idx[batch];
        float c = bd[(size_t)i0 * DD + t];
        s_c[0][t] = c;
        if (leader) bout[t] = c;
    }
    __syncthreads();

    // ---- init: exact distance to center 0 for every owned point
    #pragma unroll
    for (int j = 0; j < PPT; ++j) {
        int p = t * PPT + j;
        s_ub[p] = dist16x4_g(bd + (size_t)(pbase + p) * DD, &s_c[0][0]);
        s_lk[p] = 1;
    }
    __syncthreads();

    for (int k = 1; k < KK; ++k) {
        if (t == 0) { s_Ebits = 0u; s_wcnt = 0; }
        __syncthreads();

        // ---- (B) per-warp candidate: fully refresh the warp's max-ub point.
        //      E = max of 16 exact min_d values => E <= round winner value.
        {
            int base = wid * 128 + lane * 4;
            float4 u = *(const float4*)&s_ub[base];
            unsigned long long wb;
            {
                unsigned long long p0 = ((unsigned long long)__float_as_uint(u.x) << 32) | (unsigned)~(base + 0);
                unsigned long long p1 = ((unsigned long long)__float_as_uint(u.y) << 32) | (unsigned)~(base + 1);
                unsigned long long p2 = ((unsigned long long)__float_as_uint(u.z) << 32) | (unsigned)~(base + 2);
                unsigned long long p3 = ((unsigned long long)__float_as_uint(u.w) << 32) | (unsigned)~(base + 3);
                wb = p0 > p1 ? p0 : p1;
                wb = wb > p2 ? wb : p2;
                wb = wb > p3 ? wb : p3;
            }
            wb = warp_max_u64(wb);
            int p = (int)(~(unsigned)wb) & (PTS - 1);

            if (lane < 16)
                ((float4*)&s_pt[wid][0])[lane] =
                    __ldg(((const float4*)(bd + (size_t)(pbase + p) * DD)) + lane);
            __syncwarp();

            int   clk = s_lk[p];
            float m   = s_ub[p];
            for (int c = clk + lane; c < k; c += 32)
                m = fminf(m, dist16x4_s(&s_pt[wid][0], &s_c[c][0]));
            m = warp_min_f(m);
            if (lane == 0) {
                s_ub[p] = m;
                if (clk < k) s_lk[p] = (unsigned char)k;
                atomicMax(&s_Ebits, __float_as_uint(m));
            }
        }
        __syncthreads();
        const float E = __uint_as_float(s_Ebits);

        // ---- (C1) classify + tier-1 (lag <= LMAX): bounded serial catch-up.
        // Unrefreshed points keep ub < E <= winner -> cannot affect argmax.
        #pragma unroll
        for (int j = 0; j < PPT; ++j) {
            int p = t * PPT + j;
            float m = s_ub[p];
            int   c = s_lk[p];
            if (m >= E && c < k) {
                if (k - c <= LMAX) {
                    const float* px = bd + (size_t)(pbase + p) * DD;
                    for (; c < k; ++c)
                        m = fminf(m, dist16x4_g(px, &s_c[c][0]));
                    s_ub[p] = m;
                    s_lk[p] = (unsigned char)k;
                } else {
                    int w = atomicAdd(&s_wcnt, 1);
                    s_work[w] = (short)p;
                }
            }
        }
        __syncthreads();

        // ---- (C2) tier-2 (lag > LMAX): warp per point, lane per center.
        // Collapses the straggler tail ~32x vs thread-serial catch-up.
        const int W = s_wcnt;
        for (int i = wid; i < W; i += NW) {
            int p = s_work[i];
            if (lane < 16)
                ((float4*)&s_pt[wid][0])[lane] =
                    __ldg(((const float4*)(bd + (size_t)(pbase + p) * DD)) + lane);
            __syncwarp();
            int   clk = s_lk[p];
            float m   = s_ub[p];
            for (int c = clk + lane; c < k; c += 32)
                m = fminf(m, dist16x4_s(&s_pt[wid][0], &s_c[c][0]));
            m = warp_min_f(m);
            if (lane == 0) { s_ub[p] = m; s_lk[p] = (unsigned char)k; }
            __syncwarp();
        }
        __syncthreads();

        // ---- (D) per-batch argmax: pack (dist_bits, ~global_idx)
        unsigned long long best = 0ULL;
        #pragma unroll
        for (int j = 0; j < PPT; ++j) {
            int p = t * PPT + j;
            unsigned long long pk =
                ((unsigned long long)__float_as_uint(s_ub[p]) << 32) |
                (unsigned)~(pbase + p);
            best = (best > pk) ? best : pk;
        }
        best = warp_max_u64(best);
        if (lane == 0) s_red[wid] = best;
        __syncthreads();
        if (t == 0) {
            unsigned long long b = s_red[0];
            #pragma unroll
            for (int i = 1; i < NW; ++i) b = (b > s_red[i]) ? b : s_red[i];
            // per-batch barrier: release -> arrive -> spin -> acquire -> read
            atomicMax(&g_slot[batch * KK + k], b);
            __threadfence();
            atomicAdd(&g_cnt[batch * KK + k], 1u);
            while (atomicAdd(&g_cnt[batch * KK + k], 0u) < (unsigned)CPB)
                __nanosleep(32);
            __threadfence();
            unsigned long long v = atomicAdd(&g_slot[batch * KK + k], 0ULL);
            s_widx = (int)(~(unsigned)v);
        }
        __syncthreads();

        // ---- (E) gather winner as center k; zero its bound locally
        int w = s_widx;
        if (t < DD) {
            float c = bd[(size_t)w * DD + t];
            s_c[k][t] = c;
            if (leader) bout[k * DD + t] = c;
        }
        if (t == NT - 1) {
            int wl = w - pbase;
            if (wl >= 0 && wl < PTS) { s_ub[wl] = 0.f; s_lk[wl] = (unsigned char)KK; }
        }
        __syncthreads();
    }
}

extern "C" void kernel_launch(void* const* d_in, const int* in_sizes, int n_in,
                              void* d_out, int out_size) {
    const float* data      = (const float*)d_in[0];   // (B, N, D) fp32
    const int*   first_idx = (const int*)d_in[1];     // (B,) int32
    float*       out       = (float*)d_out;           // (B, K, D) fp32
    (void)in_sizes; (void)n_in; (void)out_size;
    km_init<<<4, NT>>>();
    kmpp_kernel<<<NCTA, NT>>>(data, first_idx, out);
}

// round 11
// speedup vs baseline: 3.1587x; 1.4280x over previous
#include <cuda_runtime.h>
#include <cuda_bf16.h>

#define BB   32
#define NN   16384
#define DD   64
#define KK   64
#define CPB  8
#define NCTA (BB*CPB)                 // 256
#define NT   512
#define NW   16
#define PTS  2048                     // points per CTA
#define PPT  4                        // points per thread
#define CROW 65                       // padded center row (conflict-free)
#define LMAX 3                        // tier-1 max lag
#define KD   16                       // dense rounds: k <= KD update everything

// ---------------- device globals (static scratch only) --------------------
__device__ unsigned long long g_slot[BB * KK];   // per (batch, round) packed argmax
__device__ unsigned int       g_cnt [BB * KK];   // per (batch, round) arrivals

__global__ void km_init() {
    int i = blockIdx.x * blockDim.x + threadIdx.x;
    if (i < BB * KK) { g_slot[i] = 0ULL; g_cnt[i] = 0u; }
}

// ---- THE distance: R1's PROVEN rounding order (rel_err 0.0 in R7-R10).
// Four sequential 16-dim fmaf chains, combined ((s0+s1)+s2)+s3.
__device__ __forceinline__ float dist16x4_g(const float* __restrict__ px,
                                            const float* __restrict__ cen) {
    float s[4];
    #pragma unroll
    for (int g = 0; g < 4; ++g) {
        float acc = 0.f;
        #pragma unroll
        for (int h = 0; h < 4; ++h) {
            float4 v = __ldg((const float4*)(px + g * 16 + h * 4));
            const int b = g * 16 + h * 4;
            float d;
            d = v.x - cen[b + 0]; acc = fmaf(d, d, acc);
            d = v.y - cen[b + 1]; acc = fmaf(d, d, acc);
            d = v.z - cen[b + 2]; acc = fmaf(d, d, acc);
            d = v.w - cen[b + 3]; acc = fmaf(d, d, acc);
        }
        s[g] = acc;
    }
    return ((s[0] + s[1]) + s[2]) + s[3];
}
__device__ __forceinline__ float dist16x4_s(const float* __restrict__ pt,
                                            const float* __restrict__ cen) {
    float s[4];
    #pragma unroll
    for (int g = 0; g < 4; ++g) {
        float acc = 0.f;
        #pragma unroll
        for (int i = 0; i < 16; ++i) {
            float d = pt[g * 16 + i] - cen[g * 16 + i];
            acc = fmaf(d, d, acc);
        }
        s[g] = acc;
    }
    return ((s[0] + s[1]) + s[2]) + s[3];
}

__device__ __forceinline__ unsigned long long warp_max_u64(unsigned long long v) {
    #pragma unroll
    for (int o = 16; o; o >>= 1) {
        unsigned long long u = __shfl_xor_sync(0xffffffffu, v, o);
        v = (v > u) ? v : u;
    }
    return v;
}
__device__ __forceinline__ float warp_min_f(float m) {
    #pragma unroll
    for (int o = 16; o; o >>= 1) m = fminf(m, __shfl_xor_sync(0xffffffffu, m, o));
    return m;
}

__global__ void __launch_bounds__(NT, 2)
kmpp_kernel(const float* __restrict__ data,
            const int*   __restrict__ first_idx,
            float*       __restrict__ out)
{
    __shared__ float s_c[KK][CROW];               // 16.6 KB: all centers
    __shared__ __align__(16) float s_ub[PTS];     //  8 KB: upper bounds on min_d
    __shared__ unsigned char s_lk[PTS];           //  2 KB: centers accounted
    __shared__ short s_work[PTS];                 //  4 KB: tier-2 worklist
    __shared__ __align__(16) float s_pt[NW][DD];  //  4 KB: per-warp staged point
    __shared__ unsigned long long s_red[NW];
    __shared__ unsigned int s_Ebits;
    __shared__ int s_widx, s_wcnt;

    const int t     = threadIdx.x;
    const int lane  = t & 31;
    const int wid   = t >> 5;
    const int cta   = blockIdx.x;
    const int batch = cta / CPB;
    const int chunk = cta % CPB;
    const int pbase = chunk * PTS;
    const float* bd = data + (size_t)batch * NN * DD;
    float* bout     = out  + (size_t)batch * KK * DD;
    const bool leader = (chunk == 0);

    // center 0
    if (t < DD) {
        int i0 = first_idx[batch];
        float c = bd[(size_t)i0 * DD + t];
        s_c[0][t] = c;
        if (leader) bout[t] = c;
    }
    __syncthreads();

    // ---- init: exact distance to center 0 for every owned point
    #pragma unroll
    for (int j = 0; j < PPT; ++j) {
        int p = t * PPT + j;
        s_ub[p] = dist16x4_g(bd + (size_t)(pbase + p) * DD, &s_c[0][0]);
        s_lk[p] = 1;
    }
    __syncthreads();

    for (int k = 1; k < KK; ++k) {
        if (k <= KD) {
            // ================= DENSE round: update every live point vs the
            // single new center (k-1). Thread-per-point, full LDG MLP.
            // E-filter prunes almost nothing at small k, so skip it.
            #pragma unroll
            for (int j = 0; j < PPT; ++j) {
                int p = t * PPT + j;
                if ((int)s_lk[p] < k) {       // lk==KK marks a selected winner
                    float m = fminf(s_ub[p],
                                    dist16x4_g(bd + (size_t)(pbase + p) * DD,
                                               &s_c[k - 1][0]));
                    s_ub[p] = m;
                    s_lk[p] = (unsigned char)k;
                }
            }
            __syncthreads();
        } else {
            // ================= FILTERED round (R10 machinery, unchanged)
            if (t == 0) { s_Ebits = 0u; s_wcnt = 0; }
            __syncthreads();

            // (B) per-warp candidate: fully refresh the warp's max-ub point.
            {
                int base = wid * 128 + lane * 4;
                float4 u = *(const float4*)&s_ub[base];
                unsigned long long wb;
                {
                    unsigned long long p0 = ((unsigned long long)__float_as_uint(u.x) << 32) | (unsigned)~(base + 0);
                    unsigned long long p1 = ((unsigned long long)__float_as_uint(u.y) << 32) | (unsigned)~(base + 1);
                    unsigned long long p2 = ((unsigned long long)__float_as_uint(u.z) << 32) | (unsigned)~(base + 2);
                    unsigned long long p3 = ((unsigned long long)__float_as_uint(u.w) << 32) | (unsigned)~(base + 3);
                    wb = p0 > p1 ? p0 : p1;
                    wb = wb > p2 ? wb : p2;
                    wb = wb > p3 ? wb : p3;
                }
                wb = warp_max_u64(wb);
                int p = (int)(~(unsigned)wb) & (PTS - 1);

                if (lane < 16)
                    ((float4*)&s_pt[wid][0])[lane] =
                        __ldg(((const float4*)(bd + (size_t)(pbase + p) * DD)) + lane);
                __syncwarp();

                int   clk = s_lk[p];
                float m   = s_ub[p];
                for (int c = clk + lane; c < k; c += 32)
                    m = fminf(m, dist16x4_s(&s_pt[wid][0], &s_c[c][0]));
                m = warp_min_f(m);
                if (lane == 0) {
                    s_ub[p] = m;
                    if (clk < k) s_lk[p] = (unsigned char)k;
                    atomicMax(&s_Ebits, __float_as_uint(m));
                }
            }
            __syncthreads();
            const float E = __uint_as_float(s_Ebits);

            // (C1) classify + tier-1 (lag <= LMAX): bounded serial catch-up.
            #pragma unroll
            for (int j = 0; j < PPT; ++j) {
                int p = t * PPT + j;
                float m = s_ub[p];
                int   c = s_lk[p];
                if (m >= E && c < k) {
                    if (k - c <= LMAX) {
                        const float* px = bd + (size_t)(pbase + p) * DD;
                        for (; c < k; ++c)
                            m = fminf(m, dist16x4_g(px, &s_c[c][0]));
                        s_ub[p] = m;
                        s_lk[p] = (unsigned char)k;
                    } else {
                        int w = atomicAdd(&s_wcnt, 1);
                        s_work[w] = (short)p;
                    }
                }
            }
            __syncthreads();

            // (C2) tier-2 (lag > LMAX): warp per point, lane per center.
            const int W = s_wcnt;
            for (int i = wid; i < W; i += NW) {
                int p = s_work[i];
                if (lane < 16)
                    ((float4*)&s_pt[wid][0])[lane] =
                        __ldg(((const float4*)(bd + (size_t)(pbase + p) * DD)) + lane);
                __syncwarp();
                int   clk = s_lk[p];
                float m   = s_ub[p];
                for (int c = clk + lane; c < k; c += 32)
                    m = fminf(m, dist16x4_s(&s_pt[wid][0], &s_c[c][0]));
                m = warp_min_f(m);
                if (lane == 0) { s_ub[p] = m; s_lk[p] = (unsigned char)k; }
                __syncwarp();
            }
            __syncthreads();
        }

        // ---- (D) per-batch argmax: pack (dist_bits, ~global_idx)
        unsigned long long best = 0ULL;
        #pragma unroll
        for (int j = 0; j < PPT; ++j) {
            int p = t * PPT + j;
            unsigned long long pk =
                ((unsigned long long)__float_as_uint(s_ub[p]) << 32) |
                (unsigned)~(pbase + p);
            best = (best > pk) ? best : pk;
        }
        best = warp_max_u64(best);
        if (lane == 0) s_red[wid] = best;
        __syncthreads();
        if (t == 0) {
            unsigned long long b = s_red[0];
            #pragma unroll
            for (int i = 1; i < NW; ++i) b = (b > s_red[i]) ? b : s_red[i];
            // per-batch barrier: release -> arrive -> spin -> acquire -> read
            atomicMax(&g_slot[batch * KK + k], b);
            __threadfence();
            atomicAdd(&g_cnt[batch * KK + k], 1u);
            while (atomicAdd(&g_cnt[batch * KK + k], 0u) < (unsigned)CPB)
                __nanosleep(32);
            __threadfence();
            unsigned long long v = atomicAdd(&g_slot[batch * KK + k], 0ULL);
            s_widx = (int)(~(unsigned)v);
        }
        __syncthreads();

        // ---- (E) gather winner as center k; zero its bound locally
        int w = s_widx;
        if (t < DD) {
            float c = bd[(size_t)w * DD + t];
            s_c[k][t] = c;
            if (leader) bout[k * DD + t] = c;
        }
        if (t == NT - 1) {
            int wl = w - pbase;
            if (wl >= 0 && wl < PTS) { s_ub[wl] = 0.f; s_lk[wl] = (unsigned char)KK; }
        }
        __syncthreads();
    }
}

extern "C" void kernel_launch(void* const* d_in, const int* in_sizes, int n_in,
                              void* d_out, int out_size) {
    const float* data      = (const float*)d_in[0];   // (B, N, D) fp32
    const int*   first_idx = (const int*)d_in[1];     // (B,) int32
    float*       out       = (float*)d_out;           // (B, K, D) fp32
    (void)in_sizes; (void)n_in; (void)out_size;
    km_init<<<4, NT>>>();
    kmpp_kernel<<<NCTA, NT>>>(data, first_idx, out);
}

// round 12
// speedup vs baseline: 3.2887x; 1.0412x over previous
#include <cuda_runtime.h>
#include <cuda_bf16.h>

#define BB   32
#define NN   16384
#define DD   64
#define KK   64
#define CPB  8
#define NCTA (BB*CPB)                 // 256
#define NT   512
#define NW   16
#define PTS  2048                     // points per CTA
#define PPT  4                        // points per thread
#define CROW 65                       // padded center row (conflict-free)
#define LMAX 3                        // tier-1 max lag
#define KD   16                       // dense rounds: k <= KD update everything

// ---------------- device globals (static scratch only) --------------------
__device__ unsigned long long g_slot[BB * KK];
__device__ unsigned int       g_cnt [BB * KK];

__global__ void km_init() {
    int i = blockIdx.x * blockDim.x + threadIdx.x;
    if (i < BB * KK) { g_slot[i] = 0ULL; g_cnt[i] = 0u; }
}

// ---- THE distance: R1's PROVEN rounding order (rel_err 0.0 in R7-R11).
// Four sequential 16-dim fmaf chains, combined ((s0+s1)+s2)+s3.
__device__ __forceinline__ float dist16x4_g(const float* __restrict__ px,
                                            const float* __restrict__ cen) {
    float s[4];
    #pragma unroll
    for (int g = 0; g < 4; ++g) {
        float acc = 0.f;
        #pragma unroll
        for (int h = 0; h < 4; ++h) {
            float4 v = __ldg((const float4*)(px + g * 16 + h * 4));
            const int b = g * 16 + h * 4;
            float d;
            d = v.x - cen[b + 0]; acc = fmaf(d, d, acc);
            d = v.y - cen[b + 1]; acc = fmaf(d, d, acc);
            d = v.z - cen[b + 2]; acc = fmaf(d, d, acc);
            d = v.w - cen[b + 3]; acc = fmaf(d, d, acc);
        }
        s[g] = acc;
    }
    return ((s[0] + s[1]) + s[2]) + s[3];
}
__device__ __forceinline__ float dist16x4_s(const float* __restrict__ pt,
                                            const float* __restrict__ cen) {
    float s[4];
    #pragma unroll
    for (int g = 0; g < 4; ++g) {
        float acc = 0.f;
        #pragma unroll
        for (int i = 0; i < 16; ++i) {
            float d = pt[g * 16 + i] - cen[g * 16 + i];
            acc = fmaf(d, d, acc);
        }
        s[g] = acc;
    }
    return ((s[0] + s[1]) + s[2]) + s[3];
}

__device__ __forceinline__ unsigned long long warp_max_u64(unsigned long long v) {
    #pragma unroll
    for (int o = 16; o; o >>= 1) {
        unsigned long long u = __shfl_xor_sync(0xffffffffu, v, o);
        v = (v > u) ? v : u;
    }
    return v;
}
__device__ __forceinline__ float warp_min_f(float m) {
    #pragma unroll
    for (int o = 16; o; o >>= 1) m = fminf(m, __shfl_xor_sync(0xffffffffu, m, o));
    return m;
}

__global__ void __launch_bounds__(NT, 2)
kmpp_kernel(const float* __restrict__ data,
            const int*   __restrict__ first_idx,
            float*       __restrict__ out)
{
    __shared__ float s_c[KK][CROW];               // 16.6 KB: all centers
    __shared__ __align__(16) float s_ub[PTS];     //  8 KB: upper bounds on min_d
    __shared__ unsigned char s_lk[PTS];           //  2 KB: centers accounted
    __shared__ short s_work[PTS];                 //  4 KB: tier-2 worklist
    __shared__ __align__(16) float s_pt[NW][DD];  //  4 KB: per-warp staged point
    __shared__ unsigned long long s_red[NW];
    __shared__ unsigned long long s_t2;           // tier-2 exact-max (packed)
    __shared__ unsigned int s_Ebits;
    __shared__ int s_widx, s_wcnt;

    const int t     = threadIdx.x;
    const int lane  = t & 31;
    const int wid   = t >> 5;
    const int cta   = blockIdx.x;
    const int batch = cta / CPB;
    const int chunk = cta % CPB;
    const int pbase = chunk * PTS;
    const float* bd = data + (size_t)batch * NN * DD;
    float* bout     = out  + (size_t)batch * KK * DD;
    const bool leader = (chunk == 0);
    const float* pxb = bd + (size_t)(pbase + t * PPT) * DD;  // my 4 points

    // center 0
    if (t < DD) {
        int i0 = first_idx[batch];
        float c = bd[(size_t)i0 * DD + t];
        s_c[0][t] = c;
        if (leader) bout[t] = c;
    }
    // ub = +inf; dense round k=1 produces d(x, c0) exactly (fmin(inf, d) = d)
    #pragma unroll
    for (int j = 0; j < PPT; ++j) {
        s_ub[t * PPT + j] = 3.4e38f;
        s_lk[t * PPT + j] = 1;
    }
    __syncthreads();

    for (int k = 1; k < KK; ++k) {
        if (k <= KD) {
            // ======== DENSE: unconditional update of all 4 points vs the new
            // center, loop-swapped (center chunk hoisted over points), fused
            // packed argmax. Winner's ub=0 self-maintains (d >= 0).
            const float* cen = &s_c[k - 1][0];
            float a[PPT][4];
            #pragma unroll
            for (int j = 0; j < PPT; ++j)
                #pragma unroll
                for (int g = 0; g < 4; ++g) a[j][g] = 0.f;

            #pragma unroll
            for (int g = 0; g < 4; ++g) {
                #pragma unroll
                for (int h = 0; h < 4; ++h) {
                    const int b = g * 16 + h * 4;
                    float c0 = cen[b + 0], c1 = cen[b + 1];
                    float c2 = cen[b + 2], c3 = cen[b + 3];
                    #pragma unroll
                    for (int j = 0; j < PPT; ++j) {
                        float4 v = __ldg((const float4*)(pxb + j * DD + b));
                        float d;
                        d = v.x - c0; a[j][g] = fmaf(d, d, a[j][g]);
                        d = v.y - c1; a[j][g] = fmaf(d, d, a[j][g]);
                        d = v.z - c2; a[j][g] = fmaf(d, d, a[j][g]);
                        d = v.w - c3; a[j][g] = fmaf(d, d, a[j][g]);
                    }
                }
            }
            unsigned long long best = 0ULL;
            #pragma unroll
            for (int j = 0; j < PPT; ++j) {
                float s = ((a[j][0] + a[j][1]) + a[j][2]) + a[j][3];
                int p = t * PPT + j;
                float m = fminf(s_ub[p], s);
                s_ub[p] = m;
                unsigned long long pk =
                    ((unsigned long long)__float_as_uint(m) << 32) |
                    (unsigned)~(pbase + p);
                best = (best > pk) ? best : pk;
            }
            best = warp_max_u64(best);
            if (lane == 0) s_red[wid] = best;
        } else {
            // ======== FILTERED (R10/R11 machinery + fused argmax)
            if (k == KD + 1) {
                // dense rounds didn't maintain lk: reconstruct (winner = KK)
                #pragma unroll
                for (int j = 0; j < PPT; ++j) {
                    int p = t * PPT + j;
                    if (s_lk[p] != (unsigned char)KK) s_lk[p] = (unsigned char)KD;
                }
            }
            if (t == 0) { s_Ebits = 0u; s_wcnt = 0; s_t2 = 0ULL; }
            __syncthreads();

            // (B) per-warp candidate: fully refresh the warp's max-ub point.
            {
                int base = wid * 128 + lane * 4;
                float4 u = *(const float4*)&s_ub[base];
                unsigned long long wb;
                {
                    unsigned long long p0 = ((unsigned long long)__float_as_uint(u.x) << 32) | (unsigned)~(base + 0);
                    unsigned long long p1 = ((unsigned long long)__float_as_uint(u.y) << 32) | (unsigned)~(base + 1);
                    unsigned long long p2 = ((unsigned long long)__float_as_uint(u.z) << 32) | (unsigned)~(base + 2);
                    unsigned long long p3 = ((unsigned long long)__float_as_uint(u.w) << 32) | (unsigned)~(base + 3);
                    wb = p0 > p1 ? p0 : p1;
                    wb = wb > p2 ? wb : p2;
                    wb = wb > p3 ? wb : p3;
                }
                wb = warp_max_u64(wb);
                int p = (int)(~(unsigned)wb) & (PTS - 1);

                if (lane < 16)
                    ((float4*)&s_pt[wid][0])[lane] =
                        __ldg(((const float4*)(bd + (size_t)(pbase + p) * DD)) + lane);
                __syncwarp();

                int   clk = s_lk[p];
                float m   = s_ub[p];
                for (int c = clk + lane; c < k; c += 32)
                    m = fminf(m, dist16x4_s(&s_pt[wid][0], &s_c[c][0]));
                m = warp_min_f(m);
                if (lane == 0) {
                    s_ub[p] = m;
                    if (clk < k) s_lk[p] = (unsigned char)k;
                    atomicMax(&s_Ebits, __float_as_uint(m));
                }
            }
            __syncthreads();
            const float E = __uint_as_float(s_Ebits);

            // (C1) classify + tier-1 catch-up, FUSED with packed argmax.
            // tier-2 points excluded here (stale overestimates); their exact
            // values enter via s_t2 in C2. Pruned points: stale < E <= winner.
            unsigned long long best = 0ULL;
            #pragma unroll
            for (int j = 0; j < PPT; ++j) {
                int p = t * PPT + j;
                float m = s_ub[p];
                int   c = s_lk[p];
                bool include = true;
                if (m >= E && c < k) {
                    if (k - c <= LMAX) {
                        const float* px = bd + (size_t)(pbase + p) * DD;
                        for (; c < k; ++c)
                            m = fminf(m, dist16x4_g(px, &s_c[c][0]));
                        s_ub[p] = m;
                        s_lk[p] = (unsigned char)k;
                    } else {
                        int w = atomicAdd(&s_wcnt, 1);
                        s_work[w] = (short)p;
                        include = false;
                    }
                }
                if (include) {
                    unsigned long long pk =
                        ((unsigned long long)__float_as_uint(m) << 32) |
                        (unsigned)~(pbase + p);
                    best = (best > pk) ? best : pk;
                }
            }
            best = warp_max_u64(best);
            if (lane == 0) s_red[wid] = best;
            __syncthreads();

            // (C2) tier-2: warp per point, lane per center; exact max -> s_t2
            const int W = s_wcnt;
            for (int i = wid; i < W; i += NW) {
                int p = s_work[i];
                if (lane < 16)
                    ((float4*)&s_pt[wid][0])[lane] =
                        __ldg(((const float4*)(bd + (size_t)(pbase + p) * DD)) + lane);
                __syncwarp();
                int   clk = s_lk[p];
                float m   = s_ub[p];
                for (int c = clk + lane; c < k; c += 32)
                    m = fminf(m, dist16x4_s(&s_pt[wid][0], &s_c[c][0]));
                m = warp_min_f(m);
                if (lane == 0) {
                    s_ub[p] = m; s_lk[p] = (unsigned char)k;
                    unsigned long long pk =
                        ((unsigned long long)__float_as_uint(m) << 32) |
                        (unsigned)~(pbase + p);
                    atomicMax(&s_t2, pk);
                }
                __syncwarp();
            }
        }

        // ======== unified tail: combine, per-batch barrier, select winner
        __syncthreads();
        if (t == 0) {
            unsigned long long b = s_red[0];
            #pragma unroll
            for (int i = 1; i < NW; ++i) b = (b > s_red[i]) ? b : s_red[i];
            if (k > KD) { unsigned long long v2 = s_t2; b = (b > v2) ? b : v2; }
            atomicMax(&g_slot[batch * KK + k], b);
            __threadfence();
            atomicAdd(&g_cnt[batch * KK + k], 1u);
            while (atomicAdd(&g_cnt[batch * KK + k], 0u) < (unsigned)CPB)
                __nanosleep(32);
            __threadfence();
            unsigned long long v = atomicAdd(&g_slot[batch * KK + k], 0ULL);
            s_widx = (int)(~(unsigned)v);
        }
        __syncthreads();

        // (E) gather winner as center k; zero its bound locally
        int w = s_widx;
        if (t < DD) {
            float c = bd[(size_t)w * DD + t];
            s_c[k][t] = c;
            if (leader) bout[k * DD + t] = c;
        }
        if (t == NT - 1) {
            int wl = w - pbase;
            if (wl >= 0 && wl < PTS) { s_ub[wl] = 0.f; s_lk[wl] = (unsigned char)KK; }
        }
        __syncthreads();
    }
}

extern "C" void kernel_launch(void* const* d_in, const int* in_sizes, int n_in,
                              void* d_out, int out_size) {
    const float* data      = (const float*)d_in[0];   // (B, N, D) fp32
    const int*   first_idx = (const int*)d_in[1];     // (B,) int32
    float*       out       = (float*)d_out;           // (B, K, D) fp32
    (void)in_sizes; (void)n_in; (void)out_size;
    km_init<<<4, NT>>>();
    kmpp_kernel<<<NCTA, NT>>>(data, first_idx, out);
}

// round 14
// speedup vs baseline: 4.4653x; 1.3578x over previous
#include <cuda_runtime.h>
#include <cuda_bf16.h>

#define BB   32
#define NN   16384
#define DD   64
#define KK   64
#define CPB  8
#define NCTA (BB*CPB)                 // 256
#define NT   512
#define NW   16
#define PTS  2048                     // points per CTA
#define PPT  4                        // points per thread
#define CROW 65                       // padded center row (conflict-free)
#define LMAX 3                        // tier-1 max lag
#define KD   16                       // dense rounds: k <= KD update everything

// ---------------- device globals (static scratch only) --------------------
__device__ unsigned long long g_slot[BB * KK];
__device__ unsigned int       g_cnt [BB * KK];

__global__ void km_init() {
    int i = blockIdx.x * blockDim.x + threadIdx.x;
    if (i < BB * KK) { g_slot[i] = 0ULL; g_cnt[i] = 0u; }
}

// ---- THE distance: R1's PROVEN rounding order (rel_err 0.0 in R7-R12).
// Four sequential 16-dim fmaf chains, combined ((s0+s1)+s2)+s3.
__device__ __forceinline__ float dist16x4_g(const float* __restrict__ px,
                                            const float* __restrict__ cen) {
    float s[4];
    #pragma unroll
    for (int g = 0; g < 4; ++g) {
        float acc = 0.f;
        #pragma unroll
        for (int h = 0; h < 4; ++h) {
            float4 v = __ldg((const float4*)(px + g * 16 + h * 4));
            const int b = g * 16 + h * 4;
            float d;
            d = v.x - cen[b + 0]; acc = fmaf(d, d, acc);
            d = v.y - cen[b + 1]; acc = fmaf(d, d, acc);
            d = v.z - cen[b + 2]; acc = fmaf(d, d, acc);
            d = v.w - cen[b + 3]; acc = fmaf(d, d, acc);
        }
        s[g] = acc;
    }
    return ((s[0] + s[1]) + s[2]) + s[3];
}
__device__ __forceinline__ float dist16x4_s(const float* __restrict__ pt,
                                            const float* __restrict__ cen) {
    float s[4];
    #pragma unroll
    for (int g = 0; g < 4; ++g) {
        float acc = 0.f;
        #pragma unroll
        for (int i = 0; i < 16; ++i) {
            float d = pt[g * 16 + i] - cen[g * 16 + i];
            acc = fmaf(d, d, acc);
        }
        s[g] = acc;
    }
    return ((s[0] + s[1]) + s[2]) + s[3];
}

__device__ __forceinline__ unsigned long long warp_max_u64(unsigned long long v) {
    #pragma unroll
    for (int o = 16; o; o >>= 1) {
        unsigned long long u = __shfl_xor_sync(0xffffffffu, v, o);
        v = (v > u) ? v : u;
    }
    return v;
}
__device__ __forceinline__ float warp_min_f(float m) {
    #pragma unroll
    for (int o = 16; o; o >>= 1) m = fminf(m, __shfl_xor_sync(0xffffffffu, m, o));
    return m;
}

__global__ void __launch_bounds__(NT, 2)
kmpp_kernel(const float* __restrict__ data,
            const int*   __restrict__ first_idx,
            float*       __restrict__ out)
{
    __shared__ float s_c[KK][CROW];               // 16.6 KB: all centers
    __shared__ __align__(16) float s_ub[PTS];     //  8 KB: upper bounds on min_d
    __shared__ unsigned char s_lk[PTS];           //  2 KB: centers accounted
    __shared__ short s_work[PTS];                 //  4 KB: tier-2 worklist
    __shared__ __align__(16) float s_pt[NW][DD];  //  4 KB: per-warp staged point
    __shared__ unsigned long long s_red[NW];
    __shared__ unsigned long long s_t2;           // tier-2 exact-max (packed)
    __shared__ unsigned int s_Ebits;
    __shared__ int s_widx, s_wcnt;

    const int t     = threadIdx.x;
    const int lane  = t & 31;
    const int wid   = t >> 5;
    const int cta   = blockIdx.x;
    const int batch = cta / CPB;
    const int chunk = cta % CPB;
    const int pbase = chunk * PTS;
    const float* bd = data + (size_t)batch * NN * DD;
    float* bout     = out  + (size_t)batch * KK * DD;
    const bool leader = (chunk == 0);

    // center 0
    if (t < DD) {
        int i0 = first_idx[batch];
        float c = bd[(size_t)i0 * DD + t];
        s_c[0][t] = c;
        if (leader) bout[t] = c;
    }
    // ub = +inf; dense round k=1 produces d(x, c0) exactly (fmin(inf, d) = d)
    #pragma unroll
    for (int j = 0; j < PPT; ++j) {
        s_ub[t * PPT + j] = 3.4e38f;
        s_lk[t * PPT + j] = 1;
    }
    __syncthreads();

    // warp-cooperative dense mapping: lane -> (point-in-tile, dim group)
    const int pl = lane >> 2;          // 0..7
    const int g  = lane & 3;           // 0..3
    const int lb = lane & ~3;          // group-base lane for shfl gathers
    const float* wbase = bd + (size_t)(pbase + wid * 128) * DD;

    for (int k = 1; k < KK; ++k) {
        if (k <= KD) {
            // ======== DENSE: warp-cooperative update of the warp's 128
            // points vs the new center. Lane computes one 16-dim group chain
            // (identical order to dist16x4), groups combined ((s0+s1)+s2)+s3
            // via shfl. Halves L1 wavefronts vs thread-per-point.
            // Center chunk loaded SCALAR (s_c rows are 4B-aligned only).
            const float* cen = &s_c[k - 1][g * 16];
            float cg[16];
            #pragma unroll
            for (int i = 0; i < 16; ++i) cg[i] = cen[i];

            unsigned long long best = 0ULL;
            #pragma unroll 2
            for (int it = 0; it < 16; ++it) {
                const int pt = it * 8 + pl;                 // point in warp tile
                const float* px = wbase + (size_t)pt * DD + g * 16;
                float4 v0 = __ldg((const float4*)(px + 0));
                float4 v1 = __ldg((const float4*)(px + 4));
                float4 v2 = __ldg((const float4*)(px + 8));
                float4 v3 = __ldg((const float4*)(px + 12));
                float acc = 0.f, d;
                d = v0.x - cg[0];  acc = fmaf(d, d, acc);
                d = v0.y - cg[1];  acc = fmaf(d, d, acc);
                d = v0.z - cg[2];  acc = fmaf(d, d, acc);
                d = v0.w - cg[3];  acc = fmaf(d, d, acc);
                d = v1.x - cg[4];  acc = fmaf(d, d, acc);
                d = v1.y - cg[5];  acc = fmaf(d, d, acc);
                d = v1.z - cg[6];  acc = fmaf(d, d, acc);
                d = v1.w - cg[7];  acc = fmaf(d, d, acc);
                d = v2.x - cg[8];  acc = fmaf(d, d, acc);
                d = v2.y - cg[9];  acc = fmaf(d, d, acc);
                d = v2.z - cg[10]; acc = fmaf(d, d, acc);
                d = v2.w - cg[11]; acc = fmaf(d, d, acc);
                d = v3.x - cg[12]; acc = fmaf(d, d, acc);
                d = v3.y - cg[13]; acc = fmaf(d, d, acc);
                d = v3.z - cg[14]; acc = fmaf(d, d, acc);
                d = v3.w - cg[15]; acc = fmaf(d, d, acc);
                // combine groups in THE proven order
                float s0 = __shfl_sync(0xffffffffu, acc, lb + 0);
                float s1 = __shfl_sync(0xffffffffu, acc, lb + 1);
                float s2 = __shfl_sync(0xffffffffu, acc, lb + 2);
                float s3 = __shfl_sync(0xffffffffu, acc, lb + 3);
                float s  = ((s0 + s1) + s2) + s3;
                if (g == 0) {
                    int p = wid * 128 + pt;
                    float m = fminf(s_ub[p], s);   // winner ub=0 self-maintains
                    s_ub[p] = m;
                    unsigned long long pk =
                        ((unsigned long long)__float_as_uint(m) << 32) |
                        (unsigned)~(pbase + p);
                    best = (best > pk) ? best : pk;
                }
            }
            best = warp_max_u64(best);             // g!=0 lanes hold 0
            if (lane == 0) s_red[wid] = best;
        } else {
            // ======== FILTERED (R12 machinery, unchanged)
            if (k == KD + 1) {
                #pragma unroll
                for (int j = 0; j < PPT; ++j) {
                    int p = t * PPT + j;
                    if (s_lk[p] != (unsigned char)KK) s_lk[p] = (unsigned char)KD;
                }
            }
            if (t == 0) { s_Ebits = 0u; s_wcnt = 0; s_t2 = 0ULL; }
            __syncthreads();

            // (B) per-warp candidate: fully refresh the warp's max-ub point.
            {
                int base = wid * 128 + lane * 4;
                float4 u = *(const float4*)&s_ub[base];
                unsigned long long wb;
                {
                    unsigned long long p0 = ((unsigned long long)__float_as_uint(u.x) << 32) | (unsigned)~(base + 0);
                    unsigned long long p1 = ((unsigned long long)__float_as_uint(u.y) << 32) | (unsigned)~(base + 1);
                    unsigned long long p2 = ((unsigned long long)__float_as_uint(u.z) << 32) | (unsigned)~(base + 2);
                    unsigned long long p3 = ((unsigned long long)__float_as_uint(u.w) << 32) | (unsigned)~(base + 3);
                    wb = p0 > p1 ? p0 : p1;
                    wb = wb > p2 ? wb : p2;
                    wb = wb > p3 ? wb : p3;
                }
                wb = warp_max_u64(wb);
                int p = (int)(~(unsigned)wb) & (PTS - 1);

                if (lane < 16)
                    ((float4*)&s_pt[wid][0])[lane] =
                        __ldg(((const float4*)(bd + (size_t)(pbase + p) * DD)) + lane);
                __syncwarp();

                int   clk = s_lk[p];
                float m   = s_ub[p];
                for (int c = clk + lane; c < k; c += 32)
                    m = fminf(m, dist16x4_s(&s_pt[wid][0], &s_c[c][0]));
                m = warp_min_f(m);
                if (lane == 0) {
                    s_ub[p] = m;
                    if (clk < k) s_lk[p] = (unsigned char)k;
                    atomicMax(&s_Ebits, __float_as_uint(m));
                }
            }
            __syncthreads();
            const float E = __uint_as_float(s_Ebits);

            // (C1) classify + tier-1 catch-up, fused with packed argmax.
            unsigned long long best = 0ULL;
            #pragma unroll
            for (int j = 0; j < PPT; ++j) {
                int p = t * PPT + j;
                float m = s_ub[p];
                int   c = s_lk[p];
                bool include = true;
                if (m >= E && c < k) {
                    if (k - c <= LMAX) {
                        const float* px = bd + (size_t)(pbase + p) * DD;
                        for (; c < k; ++c)
                            m = fminf(m, dist16x4_g(px, &s_c[c][0]));
                        s_ub[p] = m;
                        s_lk[p] = (unsigned char)k;
                    } else {
                        int w = atomicAdd(&s_wcnt, 1);
                        s_work[w] = (short)p;
                        include = false;
                    }
                }
                if (include) {
                    unsigned long long pk =
                        ((unsigned long long)__float_as_uint(m) << 32) |
                        (unsigned)~(pbase + p);
                    best = (best > pk) ? best : pk;
                }
            }
            best = warp_max_u64(best);
            if (lane == 0) s_red[wid] = best;
            __syncthreads();

            // (C2) tier-2: warp per point, lane per center; exact max -> s_t2
            const int W = s_wcnt;
            for (int i = wid; i < W; i += NW) {
                int p = s_work[i];
                if (lane < 16)
                    ((float4*)&s_pt[wid][0])[lane] =
                        __ldg(((const float4*)(bd + (size_t)(pbase + p) * DD)) + lane);
                __syncwarp();
                int   clk = s_lk[p];
                float m   = s_ub[p];
                for (int c = clk + lane; c < k; c += 32)
                    m = fminf(m, dist16x4_s(&s_pt[wid][0], &s_c[c][0]));
                m = warp_min_f(m);
                if (lane == 0) {
                    s_ub[p] = m; s_lk[p] = (unsigned char)k;
                    unsigned long long pk =
                        ((unsigned long long)__float_as_uint(m) << 32) |
                        (unsigned)~(pbase + p);
                    atomicMax(&s_t2, pk);
                }
                __syncwarp();
            }
        }

        // ======== unified tail: combine, per-batch barrier, select winner
        __syncthreads();
        if (t == 0) {
            unsigned long long b = s_red[0];
            #pragma unroll
            for (int i = 1; i < NW; ++i) b = (b > s_red[i]) ? b : s_red[i];
            if (k > KD) { unsigned long long v2 = s_t2; b = (b > v2) ? b : v2; }
            atomicMax(&g_slot[batch * KK + k], b);
            __threadfence();
            atomicAdd(&g_cnt[batch * KK + k], 1u);
            while (atomicAdd(&g_cnt[batch * KK + k], 0u) < (unsigned)CPB)
                __nanosleep(32);
            __threadfence();
            unsigned long long v = atomicAdd(&g_slot[batch * KK + k], 0ULL);
            s_widx = (int)(~(unsigned)v);
        }
        __syncthreads();

        // (E) gather winner as center k; zero its bound locally
        int w = s_widx;
        if (t < DD) {
            float c = bd[(size_t)w * DD + t];
            s_c[k][t] = c;
            if (leader) bout[k * DD + t] = c;
        }
        if (t == NT - 1) {
            int wl = w - pbase;
            if (wl >= 0 && wl < PTS) { s_ub[wl] = 0.f; s_lk[wl] = (unsigned char)KK; }
        }
        __syncthreads();
    }
}

extern "C" void kernel_launch(void* const* d_in, const int* in_sizes, int n_in,
                              void* d_out, int out_size) {
    const float* data      = (const float*)d_in[0];   // (B, N, D) fp32
    const int*   first_idx = (const int*)d_in[1];     // (B,) int32
    float*       out       = (float*)d_out;           // (B, K, D) fp32
    (void)in_sizes; (void)n_in; (void)out_size;
    km_init<<<4, NT>>>();
    kmpp_kernel<<<NCTA, NT>>>(data, first_idx, out);
}

// round 15
// speedup vs baseline: 4.5051x; 1.0089x over previous
#include <cuda_runtime.h>
#include <cuda_bf16.h>

#define BB   32
#define NN   16384
#define DD   64
#define KK   64
#define CPB  8
#define NCTA (BB*CPB)                 // 256
#define NT   512
#define NW   16
#define PTS  2048                     // points per CTA
#define PPT  4                        // points per thread
#define CROW 65                       // padded center row (conflict-free)
#define LMAX 3                        // tier-1 max lag
#define KD   16                       // dense rounds: k <= KD update everything

// ---------------- device globals (static scratch only) --------------------
// One slot per (batch, round, chunk). The packed value IS the message
// (low word = ~idx != 0), so a single word store/poll synchronizes a round.
__device__ unsigned long long g_part[BB * KK * CPB];   // 128 KB

__global__ void km_init() {
    int i = blockIdx.x * blockDim.x + threadIdx.x;
    if (i < BB * KK * CPB) g_part[i] = 0ULL;
}

// 32-byte read-only global load (256-bit). Pure; bits land unchanged.
__device__ __forceinline__ void ld256(const float* p, float4& a, float4& b) {
    unsigned long long x, y, z, w;
    asm("ld.global.nc.v4.b64 {%0,%1,%2,%3}, [%4];"
        : "=l"(x), "=l"(y), "=l"(z), "=l"(w) : "l"(p));
    a.x = __uint_as_float((unsigned)x);  a.y = __uint_as_float((unsigned)(x >> 32));
    a.z = __uint_as_float((unsigned)y);  a.w = __uint_as_float((unsigned)(y >> 32));
    b.x = __uint_as_float((unsigned)z);  b.y = __uint_as_float((unsigned)(z >> 32));
    b.z = __uint_as_float((unsigned)w);  b.w = __uint_as_float((unsigned)(w >> 32));
}

// ---- THE distance: R1's PROVEN rounding order (rel_err 0.0 in R7-R14).
// Four sequential 16-dim fmaf chains, combined ((s0+s1)+s2)+s3.
__device__ __forceinline__ float dist16x4_g(const float* __restrict__ px,
                                            const float* __restrict__ cen) {
    float s[4];
    #pragma unroll
    for (int g = 0; g < 4; ++g) {
        float4 v0, v1, v2, v3;
        ld256(px + g * 16,     v0, v1);
        ld256(px + g * 16 + 8, v2, v3);
        const int b = g * 16;
        float acc = 0.f, d;
        d = v0.x - cen[b + 0];  acc = fmaf(d, d, acc);
        d = v0.y - cen[b + 1];  acc = fmaf(d, d, acc);
        d = v0.z - cen[b + 2];  acc = fmaf(d, d, acc);
        d = v0.w - cen[b + 3];  acc = fmaf(d, d, acc);
        d = v1.x - cen[b + 4];  acc = fmaf(d, d, acc);
        d = v1.y - cen[b + 5];  acc = fmaf(d, d, acc);
        d = v1.z - cen[b + 6];  acc = fmaf(d, d, acc);
        d = v1.w - cen[b + 7];  acc = fmaf(d, d, acc);
        d = v2.x - cen[b + 8];  acc = fmaf(d, d, acc);
        d = v2.y - cen[b + 9];  acc = fmaf(d, d, acc);
        d = v2.z - cen[b + 10]; acc = fmaf(d, d, acc);
        d = v2.w - cen[b + 11]; acc = fmaf(d, d, acc);
        d = v3.x - cen[b + 12]; acc = fmaf(d, d, acc);
        d = v3.y - cen[b + 13]; acc = fmaf(d, d, acc);
        d = v3.z - cen[b + 14]; acc = fmaf(d, d, acc);
        d = v3.w - cen[b + 15]; acc = fmaf(d, d, acc);
        s[g] = acc;
    }
    return ((s[0] + s[1]) + s[2]) + s[3];
}
__device__ __forceinline__ float dist16x4_s(const float* __restrict__ pt,
                                            const float* __restrict__ cen) {
    float s[4];
    #pragma unroll
    for (int g = 0; g < 4; ++g) {
        float acc = 0.f;
        #pragma unroll
        for (int i = 0; i < 16; ++i) {
            float d = pt[g * 16 + i] - cen[g * 16 + i];
            acc = fmaf(d, d, acc);
        }
        s[g] = acc;
    }
    return ((s[0] + s[1]) + s[2]) + s[3];
}

__device__ __forceinline__ unsigned long long warp_max_u64(unsigned long long v) {
    #pragma unroll
    for (int o = 16; o; o >>= 1) {
        unsigned long long u = __shfl_xor_sync(0xffffffffu, v, o);
        v = (v > u) ? v : u;
    }
    return v;
}
__device__ __forceinline__ float warp_min_f(float m) {
    #pragma unroll
    for (int o = 16; o; o >>= 1) m = fminf(m, __shfl_xor_sync(0xffffffffu, m, o));
    return m;
}

__global__ void __launch_bounds__(NT, 2)
kmpp_kernel(const float* __restrict__ data,
            const int*   __restrict__ first_idx,
            float*       __restrict__ out)
{
    __shared__ float s_c[KK][CROW];               // 16.6 KB: all centers
    __shared__ __align__(16) float s_ub[PTS];     //  8 KB: upper bounds on min_d
    __shared__ unsigned char s_lk[PTS];           //  2 KB: centers accounted
    __shared__ short s_work[PTS];                 //  4 KB: tier-2 worklist
    __shared__ __align__(16) float s_pt[NW][DD];  //  4 KB: per-warp staged point
    __shared__ unsigned long long s_red[NW];
    __shared__ unsigned long long s_parts[CPB];   // polled peer contributions
    __shared__ unsigned long long s_t2;           // tier-2 exact-max (packed)
    __shared__ unsigned int s_Ebits;
    __shared__ int s_widx, s_wcnt;

    const int t     = threadIdx.x;
    const int lane  = t & 31;
    const int wid   = t >> 5;
    const int cta   = blockIdx.x;
    const int batch = cta / CPB;
    const int chunk = cta % CPB;
    const int pbase = chunk * PTS;
    const float* bd = data + (size_t)batch * NN * DD;
    float* bout     = out  + (size_t)batch * KK * DD;
    const bool leader = (chunk == 0);

    // center 0
    if (t < DD) {
        int i0 = first_idx[batch];
        float c = bd[(size_t)i0 * DD + t];
        s_c[0][t] = c;
        if (leader) bout[t] = c;
    }
    // ub = +inf; dense round k=1 produces d(x, c0) exactly (fmin(inf, d) = d)
    #pragma unroll
    for (int j = 0; j < PPT; ++j) {
        s_ub[t * PPT + j] = 3.4e38f;
        s_lk[t * PPT + j] = 1;
    }
    __syncthreads();

    // warp-cooperative dense mapping: lane -> (point-in-tile, dim group)
    const int pl = lane >> 2;          // 0..7
    const int g  = lane & 3;           // 0..3
    const int lb = lane & ~3;          // group-base lane for shfl gathers
    const float* wbase = bd + (size_t)(pbase + wid * 128) * DD;

    for (int k = 1; k < KK; ++k) {
        if (k <= KD) {
            // ======== DENSE: warp-cooperative update of the warp's 128
            // points vs the new center. Lane computes one 16-dim group chain
            // (identical order to dist16x4), groups combined ((s0+s1)+s2)+s3
            // via shfl. 256-bit loads: 2 LDG per group instead of 4.
            const float* cen = &s_c[k - 1][g * 16];
            float cg[16];
            #pragma unroll
            for (int i = 0; i < 16; ++i) cg[i] = cen[i];

            unsigned long long best = 0ULL;
            #pragma unroll 2
            for (int it = 0; it < 16; ++it) {
                const int pt = it * 8 + pl;                 // point in warp tile
                const float* px = wbase + (size_t)pt * DD + g * 16;
                float4 v0, v1, v2, v3;
                ld256(px,     v0, v1);
                ld256(px + 8, v2, v3);
                float acc = 0.f, d;
                d = v0.x - cg[0];  acc = fmaf(d, d, acc);
                d = v0.y - cg[1];  acc = fmaf(d, d, acc);
                d = v0.z - cg[2];  acc = fmaf(d, d, acc);
                d = v0.w - cg[3];  acc = fmaf(d, d, acc);
                d = v1.x - cg[4];  acc = fmaf(d, d, acc);
                d = v1.y - cg[5];  acc = fmaf(d, d, acc);
                d = v1.z - cg[6];  acc = fmaf(d, d, acc);
                d = v1.w - cg[7];  acc = fmaf(d, d, acc);
                d = v2.x - cg[8];  acc = fmaf(d, d, acc);
                d = v2.y - cg[9];  acc = fmaf(d, d, acc);
                d = v2.z - cg[10]; acc = fmaf(d, d, acc);
                d = v2.w - cg[11]; acc = fmaf(d, d, acc);
                d = v3.x - cg[12]; acc = fmaf(d, d, acc);
                d = v3.y - cg[13]; acc = fmaf(d, d, acc);
                d = v3.z - cg[14]; acc = fmaf(d, d, acc);
                d = v3.w - cg[15]; acc = fmaf(d, d, acc);
                // combine groups in THE proven order
                float s0 = __shfl_sync(0xffffffffu, acc, lb + 0);
                float s1 = __shfl_sync(0xffffffffu, acc, lb + 1);
                float s2 = __shfl_sync(0xffffffffu, acc, lb + 2);
                float s3 = __shfl_sync(0xffffffffu, acc, lb + 3);
                float s  = ((s0 + s1) + s2) + s3;
                if (g == 0) {
                    int p = wid * 128 + pt;
                    float m = fminf(s_ub[p], s);   // winner ub=0 self-maintains
                    s_ub[p] = m;
                    unsigned long long pk =
                        ((unsigned long long)__float_as_uint(m) << 32) |
                        (unsigned)~(pbase + p);
                    best = (best > pk) ? best : pk;
                }
            }
            best = warp_max_u64(best);             // g!=0 lanes hold 0
            if (lane == 0) s_red[wid] = best;
        } else {
            // ======== FILTERED (R14 machinery, unchanged)
            if (k == KD + 1) {
                #pragma unroll
                for (int j = 0; j < PPT; ++j) {
                    int p = t * PPT + j;
                    if (s_lk[p] != (unsigned char)KK) s_lk[p] = (unsigned char)KD;
                }
            }
            if (t == 0) { s_Ebits = 0u; s_wcnt = 0; s_t2 = 0ULL; }
            __syncthreads();

            // (B) per-warp candidate: fully refresh the warp's max-ub point.
            {
                int base = wid * 128 + lane * 4;
                float4 u = *(const float4*)&s_ub[base];
                unsigned long long wb;
                {
                    unsigned long long p0 = ((unsigned long long)__float_as_uint(u.x) << 32) | (unsigned)~(base + 0);
                    unsigned long long p1 = ((unsigned long long)__float_as_uint(u.y) << 32) | (unsigned)~(base + 1);
                    unsigned long long p2 = ((unsigned long long)__float_as_uint(u.z) << 32) | (unsigned)~(base + 2);
                    unsigned long long p3 = ((unsigned long long)__float_as_uint(u.w) << 32) | (unsigned)~(base + 3);
                    wb = p0 > p1 ? p0 : p1;
                    wb = wb > p2 ? wb : p2;
                    wb = wb > p3 ? wb : p3;
                }
                wb = warp_max_u64(wb);
                int p = (int)(~(unsigned)wb) & (PTS - 1);

                if (lane < 16)
                    ((float4*)&s_pt[wid][0])[lane] =
                        __ldg(((const float4*)(bd + (size_t)(pbase + p) * DD)) + lane);
                __syncwarp();

                int   clk = s_lk[p];
                float m   = s_ub[p];
                for (int c = clk + lane; c < k; c += 32)
                    m = fminf(m, dist16x4_s(&s_pt[wid][0], &s_c[c][0]));
                m = warp_min_f(m);
                if (lane == 0) {
                    s_ub[p] = m;
                    if (clk < k) s_lk[p] = (unsigned char)k;
                    atomicMax(&s_Ebits, __float_as_uint(m));
                }
            }
            __syncthreads();
            const float E = __uint_as_float(s_Ebits);

            // (C1) classify + tier-1 catch-up, fused with packed argmax.
            unsigned long long best = 0ULL;
            #pragma unroll
            for (int j = 0; j < PPT; ++j) {
                int p = t * PPT + j;
                float m = s_ub[p];
                int   c = s_lk[p];
                bool include = true;
                if (m >= E && c < k) {
                    if (k - c <= LMAX) {
                        const float* px = bd + (size_t)(pbase + p) * DD;
                        for (; c < k; ++c)
                            m = fminf(m, dist16x4_g(px, &s_c[c][0]));
                        s_ub[p] = m;
                        s_lk[p] = (unsigned char)k;
                    } else {
                        int w = atomicAdd(&s_wcnt, 1);
                        s_work[w] = (short)p;
                        include = false;
                    }
                }
                if (include) {
                    unsigned long long pk =
                        ((unsigned long long)__float_as_uint(m) << 32) |
                        (unsigned)~(pbase + p);
                    best = (best > pk) ? best : pk;
                }
            }
            best = warp_max_u64(best);
            if (lane == 0) s_red[wid] = best;
            __syncthreads();

            // (C2) tier-2: warp per point, lane per center; exact max -> s_t2
            const int W = s_wcnt;
            for (int i = wid; i < W; i += NW) {
                int p = s_work[i];
                if (lane < 16)
                    ((float4*)&s_pt[wid][0])[lane] =
                        __ldg(((const float4*)(bd + (size_t)(pbase + p) * DD)) + lane);
                __syncwarp();
                int   clk = s_lk[p];
                float m   = s_ub[p];
                for (int c = clk + lane; c < k; c += 32)
                    m = fminf(m, dist16x4_s(&s_pt[wid][0], &s_c[c][0]));
                m = warp_min_f(m);
                if (lane == 0) {
                    s_ub[p] = m; s_lk[p] = (unsigned char)k;
                    unsigned long long pk =
                        ((unsigned long long)__float_as_uint(m) << 32) |
                        (unsigned)~(pbase + p);
                    atomicMax(&s_t2, pk);
                }
                __syncwarp();
            }
        }

        // ======== tail: single-word broadcast barrier, select winner
        __syncthreads();
        if (t == 0) {
            unsigned long long b = s_red[0];
            #pragma unroll
            for (int i = 1; i < NW; ++i) b = (b > s_red[i]) ? b : s_red[i];
            if (k > KD) { unsigned long long v2 = s_t2; b = (b > v2) ? b : v2; }
            // post my contribution: the word itself is the message (nonzero)
            atomicExch(&g_part[(batch * KK + k) * CPB + chunk], b);
        }
        if (t < CPB) {
            volatile unsigned long long* sp =
                (volatile unsigned long long*)&g_part[(batch * KK + k) * CPB + t];
            unsigned long long v;
            while ((v = *sp) == 0ULL) { __nanosleep(32); }
            s_parts[t] = v;
        }
        __syncthreads();
        if (t == 0) {
            unsigned long long b = s_parts[0];
            #pragma unroll
            for (int i = 1; i < CPB; ++i) b = (b > s_parts[i]) ? b : s_parts[i];
            s_widx = (int)(~(unsigned)b);
        }
        __syncthreads();

        // (E) gather winner as center k; zero its bound locally
        int w = s_widx;
        if (t < DD) {
            float c = bd[(size_t)w * DD + t];
            s_c[k][t] = c;
            if (leader) bout[k * DD + t] = c;
        }
        if (t == NT - 1) {
            int wl = w - pbase;
            if (wl >= 0 && wl < PTS) { s_ub[wl] = 0.f; s_lk[wl] = (unsigned char)KK; }
        }
        __syncthreads();
    }
}

extern "C" void kernel_launch(void* const* d_in, const int* in_sizes, int n_in,
                              void* d_out, int out_size) {
    const float* data      = (const float*)d_in[0];   // (B, N, D) fp32
    const int*   first_idx = (const int*)d_in[1];     // (B,) int32
    float*       out       = (float*)d_out;           // (B, K, D) fp32
    (void)in_sizes; (void)n_in; (void)out_size;
    km_init<<<32, NT>>>();
    kmpp_kernel<<<NCTA, NT>>>(data, first_idx, out);
}